// round 16
// baseline (speedup 1.0000x reference)
#include <cuda_runtime.h>

#define Hh 256
#define Ww 256
#define Bn 8
#define Fn 64
#define HW 65536
#define PBLK 128

// ---------------- device globals -------------------------------------------
__device__ float g_xA[HW];
__device__ float g_xB[HW];
__device__ float4 g_part4[2][PBLK];
__device__ float g_p1[4][Bn * HW];       // pass1 filter-group partials (8MB)
__device__ float g_sigma, g_lambda, g_tau;
__device__ unsigned g_barcnt = 0;        // invariant 0 between barriers
__device__ unsigned g_bargen = 0;        // monotone generation (replay-safe)

// ---------------- float4 helpers ---------------------------------------------
__device__ __forceinline__ void ld4cs(float d[4], const float* p) {
    float4 v = __ldcs((const float4*)p); d[0]=v.x; d[1]=v.y; d[2]=v.z; d[3]=v.w;
}
__device__ __forceinline__ void st4cs(float* p, const float d[4]) {
    __stcs((float4*)p, make_float4(d[0], d[1], d[2], d[3]));
}

// ---------------- profile-shift no-ops (keep k_pass1 the 4th launch) ---------
__global__ void k_nop() {}

// ---------------- grid barrier over the PBLK power blocks --------------------
__device__ __forceinline__ void grid_bar()
{
    __syncthreads();
    if (threadIdx.x == 0) {
        volatile unsigned* genp = &g_bargen;
        unsigned gen = *genp;              // read BEFORE arriving
        unsigned a = atomicAdd(&g_barcnt, 1u);
        if (a == PBLK - 1u) {
            atomicExch(&g_barcnt, 0u);     // reset BEFORE releasing
            __threadfence();
            atomicExch(&g_bargen, gen + 1u);
        } else {
            while (*genp == gen) { __nanosleep(32); }
        }
        __threadfence();
    }
    __syncthreads();
}

// ---------------- one application of M (rolling 5x5 register window) ---------
template<int N, int OWN>
__device__ __forceinline__ void apply_app(
    const float* __restrict__ src, float* __restrict__ dst,
    int dst_lo_g, int src_lo_g, int j, const float G[25],
    const float* __restrict__ sK, const float* __restrict__ sCL,
    const float* __restrict__ sCR, float& sacc, float* __restrict__ gdst)
{
    float win[5][5];
    #pragma unroll
    for (int r = 0; r < 4; r++)
        #pragma unroll
        for (int c = 0; c < 5; c++)
            win[r+1][c] = src[r*260 + j + c];

    #pragma unroll
    for (int rr = 0; rr < N; rr++) {
        const int r = dst_lo_g + rr;
        #pragma unroll
        for (int q = 0; q < 4; q++)
            #pragma unroll
            for (int c = 0; c < 5; c++)
                win[q][c] = win[q+1][c];
        #pragma unroll
        for (int c = 0; c < 5; c++)
            win[4][c] = src[(rr + 4)*260 + j + c];

        float z = 0.f;
        if (r >= 0 && r < 256) {
            #pragma unroll
            for (int di = 0; di < 5; di++)
                #pragma unroll
                for (int dj = 0; dj < 5; dj++)
                    z = fmaf(G[di*5 + dj], win[di][dj], z);

            if (r == 0 || r == 255) {
                #pragma unroll
                for (int ai = 0; ai < 3; ai++)
                    #pragma unroll
                    for (int aj = 0; aj < 3; aj++) {
                        int pi = r + ai - 1, pj = j + aj - 1;
                        if (pi < 0 || pi > 255 || pj < 0 || pj > 255) {
                            #pragma unroll
                            for (int bi = 0; bi < 3; bi++)
                                #pragma unroll
                                for (int bj = 0; bj < 3; bj++) {
                                    int qi = pi + bi - 1, qj = pj + bj - 1;
                                    if (qi >= 0 && qi < 256 && qj >= 0 && qj < 256)
                                        z -= sK[(ai*3+aj)*9 + bi*3 + bj] *
                                             src[(qi - src_lo_g)*260 + qj + 2];
                                }
                        }
                    }
            } else if (j == 0) {
                #pragma unroll
                for (int d = 0; d < 5; d++) {
                    int qi = r + d - 2;
                    if (qi >= 0 && qi < 256)
                        z = fmaf(-sCL[d], win[d][2], z);
                }
            } else if (j == 255) {
                #pragma unroll
                for (int d = 0; d < 5; d++) {
                    int qi = r + d - 2;
                    if (qi >= 0 && qi < 256)
                        z = fmaf(-sCR[d], win[d][2], z);
                }
            }
        }
        dst[rr*260 + 2 + j] = z;
        if (rr == OWN || rr == OWN + 1) {
            sacc = fmaf(z, z, sacc);
            if (gdst) gdst[r*256 + j] = z;
        }
    }
}

// ---------------- power iteration (R6 — proven 32us) --------------------------
__global__ void __launch_bounds__(256) k_power(
    const float* __restrict__ w, const float* __restrict__ beta,
    const float* __restrict__ lambd, const float* __restrict__ lsig)
{
    __shared__ float pool[6380];
    float* bufA = pool;                 // 14 x 260
    float* bufB = pool + 3640;          // 10 x 260
    float* sK   = pool + 6240;          // 81
    float* sG   = pool + 6321;          // 25
    float* sCL  = pool + 6346;          // 5
    float* sCR  = pool + 6351;          // 5
    float* red  = pool + 6356;          // 3 x 8

    const int t = threadIdx.x, blk = blockIdx.x;
    const int j = t, lane = t & 31, warp = t >> 5;
    const int i0 = blk * 2;

    if (t < 81) {
        int a9 = t / 9, b9 = t % 9;
        int ai = a9 / 3, aj = a9 % 3;
        int bi = b9 / 3, bj = b9 % 3;
        float s = 0.f;
        #pragma unroll 8
        for (int f = 0; f < Fn; f++)
            s += w[f*9 + (2-ai)*3 + (2-aj)] * w[f*9 + bi*3 + bj];
        sK[t] = s;
    }
    __syncthreads();
    if (t < 25) {
        int di = t / 5 - 2, dj = t % 5 - 2;
        float s = 0.f;
        for (int a9 = 0; a9 < 9; a9++) {
            int ai = a9/3 - 1, aj = a9%3 - 1;
            int bi = di - ai, bj = dj - aj;
            if (bi >= -1 && bi <= 1 && bj >= -1 && bj <= 1)
                s += sK[a9*9 + (bi+1)*3 + (bj+1)];
        }
        sG[t] = s;
    } else if (t >= 32 && t < 37) {
        int d = t - 32;
        float s = 0.f;
        for (int ai = 0; ai < 3; ai++) {
            int bi = d - ai;
            if (bi >= 0 && bi <= 2) s += sK[(ai*3 + 0)*9 + bi*3 + 2];
        }
        sCL[d] = s;
    } else if (t >= 40 && t < 45) {
        int d = t - 40;
        float s = 0.f;
        for (int ai = 0; ai < 3; ai++) {
            int bi = d - ai;
            if (bi >= 0 && bi <= 2) s += sK[(ai*3 + 2)*9 + bi*3 + 0];
        }
        sCR[d] = s;
    } else if (t == 255 && blk == 0) {
        g_sigma  = expf(lsig[0]) + 0.05f;
        g_lambda = lambd[0];
    }
    if (t >= 64 && t < 78) {
        int q = t - 64;
        bufA[q*260] = bufA[q*260+1] = bufA[q*260+258] = bufA[q*260+259] = 0.f;
    } else if (t >= 96 && t < 106) {
        int q = t - 96;
        bufB[q*260] = bufB[q*260+1] = bufB[q*260+258] = bufB[q*260+259] = 0.f;
    }
    __syncthreads();

    float G[25];
    #pragma unroll
    for (int k = 0; k < 25; k++) G[k] = sG[k];

    g_xA[i0*256 + j]     = 1.f / 256.f;
    g_xA[(i0+1)*256 + j] = 1.f / 256.f;
    __threadfence();
    grid_bar();

    float val = 1.f, inv = 1.f;
    int iter = 0, par = 0;
    bool done = false;

    while (!done) {
        const float* srcg = par ? g_xB : g_xA;
        float*       dstg = par ? g_xA : g_xB;

        __syncthreads();
        #pragma unroll
        for (int rr = 0; rr < 14; rr++) {
            int gi = i0 - 6 + rr;
            bufA[rr*260 + 2 + j] =
                (gi >= 0 && gi < 256) ? inv * __ldcg(&srcg[gi*256 + j]) : 0.f;
        }
        __syncthreads();

        float s1 = 0.f, s2 = 0.f, s3 = 0.f;
        apply_app<10,4>(bufA, bufB, i0-4, i0-6, j, G, sK, sCL, sCR, s1, nullptr);
        __syncthreads();
        apply_app<6,2>(bufB, bufA, i0-2, i0-4, j, G, sK, sCL, sCR, s2, nullptr);
        __syncthreads();
        apply_app<2,0>(bufA, bufB, i0,   i0-2, j, G, sK, sCL, sCR, s3, dstg);

        #pragma unroll
        for (int o = 16; o > 0; o >>= 1) {
            s1 += __shfl_xor_sync(0xffffffffu, s1, o);
            s2 += __shfl_xor_sync(0xffffffffu, s2, o);
            s3 += __shfl_xor_sync(0xffffffffu, s3, o);
        }
        if (lane == 0) { red[0*8+warp] = s1; red[1*8+warp] = s2; red[2*8+warp] = s3; }
        __syncthreads();
        if (t == 0) {
            float a = 0.f, b = 0.f, c = 0.f;
            #pragma unroll
            for (int w8 = 0; w8 < 8; w8++) {
                a += red[0*8+w8]; b += red[1*8+w8]; c += red[2*8+w8];
            }
            g_part4[par][blk] = make_float4(a, b, c, 0.f);
        }
        __threadfence();
        grid_bar();

        float px = 0.f, py = 0.f, pz = 0.f;
        if (t < 128) {
            px = __ldcg(&g_part4[par][t].x);
            py = __ldcg(&g_part4[par][t].y);
            pz = __ldcg(&g_part4[par][t].z);
        }
        #pragma unroll
        for (int o = 16; o > 0; o >>= 1) {
            px += __shfl_xor_sync(0xffffffffu, px, o);
            py += __shfl_xor_sync(0xffffffffu, py, o);
            pz += __shfl_xor_sync(0xffffffffu, pz, o);
        }
        __syncthreads();
        if (lane == 0 && t < 128) { red[0*8+warp] = px; red[1*8+warp] = py; red[2*8+warp] = pz; }
        __syncthreads();
        float S1 = red[0*8+0] + red[0*8+1] + red[0*8+2] + red[0*8+3];
        float S2 = red[1*8+0] + red[1*8+1] + red[1*8+2] + red[1*8+3];
        float S3 = red[2*8+0] + red[2*8+1] + red[2*8+2] + red[2*8+3];

        float v1 = sqrtf(S1);
        float v2 = sqrtf(S2) / v1;
        float v3 = sqrtf(S3) / sqrtf(S2);
        float rel;
        iter++; rel = fabsf(v1 - val) / val; val = v1;
        if (iter >= 300 || rel < 1e-4f) { done = true; }
        else {
            iter++; rel = fabsf(v2 - val) / val; val = v2;
            if (iter >= 300 || rel < 1e-4f) { done = true; }
            else {
                iter++; rel = fabsf(v3 - val) / val; val = v3;
                if (iter >= 300 || rel < 1e-4f) done = true;
            }
        }
        inv = 1.f / sqrtf(S3);
        par ^= 1;
    }

    if (blk == 0 && t == 0) {
        float sg = expf(lsig[0]) + 0.05f;
        g_tau = 0.99f / (beta[0] * 0.5f + sg * val);
    }
}

// ---------------- pass 1: smem-free, shuffle halo exchange --------------------
// partial[fg] = tau * sum_{f in fg} convT(u_f); thread = 1 row x 4 cols
__global__ void __launch_bounds__(256) k_pass1(
    const float* __restrict__ u_in, const float* __restrict__ w)
{
    const int t    = threadIdx.x;
    const int lane = t & 31;
    const int q    = blockIdx.x;
    const int fg   = q & 3;
    const int rt   = (q >> 2) & 63;
    const int b    = q >> 8;
    const int i0   = rt * 4;
    const int qc   = t & 63;        // cols 4qc..4qc+3
    const int rl   = t >> 6;        // own row within tile
    const int gi   = i0 + rl;
    const int col  = 4 * qc;
    const float tau = g_tau;

    float acc[4] = {0.f, 0.f, 0.f, 0.f};

    for (int ff = 0; ff < 16; ff++) {
        const int f = fg * 16 + ff;
        const float* uf = u_in + (size_t)(b*Fn + f) * HW;

        // 3x6 window: 3 LDG.128 + shuffle halos (+ predicated edge scalars)
        float win[3][6];
        #pragma unroll
        for (int rr = 0; rr < 3; rr++) {
            int r = gi - 1 + rr;
            bool ok = (r >= 0 && r < Hh);
            const float* row = uf + r * Ww + col;
            float4 v = ok ? *(const float4*)row
                          : make_float4(0.f, 0.f, 0.f, 0.f);
            // neighbor lanes hold the adjacent float4 of the SAME row r
            float lf = __shfl_up_sync(0xffffffffu, v.w, 1);
            float rg = __shfl_down_sync(0xffffffffu, v.x, 1);
            if (lane == 0)  lf = (ok && col > 0)      ? row[-1] : 0.f;
            if (lane == 31) rg = (ok && col + 4 < Ww) ? row[4]  : 0.f;
            win[rr][0] = lf;
            win[rr][1] = v.x; win[rr][2] = v.y; win[rr][3] = v.z; win[rr][4] = v.w;
            win[rr][5] = rg;
        }

        float m[3][3];
        #pragma unroll
        for (int au = 0; au < 3; au++)
            #pragma unroll
            for (int ac = 0; ac < 3; ac++)
                m[au][ac] = tau * __ldg(&w[f*9 + (2-au)*3 + (2-ac)]);

        #pragma unroll
        for (int cc = 0; cc < 4; cc++)
            #pragma unroll
            for (int au = 0; au < 3; au++)
                #pragma unroll
                for (int ac = 0; ac < 3; ac++)
                    acc[cc] = fmaf(m[au][ac], win[au][cc + ac], acc[cc]);
    }

    *(float4*)&g_p1[fg][b*HW + gi*Ww + col] =
        make_float4(acc[0], acc[1], acc[2], acc[3]);
}

// ---------------- combine: out0 = clip(x - tau*(HtH.x - bias) - sum(p)) -------
__global__ void k_p1c(const float* __restrict__ x_in,
                      const float* __restrict__ bias,
                      const float* __restrict__ HtH,
                      float* __restrict__ out0)
{
    int idx = blockIdx.x * 256 + threadIdx.x;   // float4 index; 512*256 = 131072
    int hwq = idx & (HW/4 - 1);                 // position within one image (float4)
    float tau = g_tau;
    float4 x4 = ((const float4*)x_in)[idx];
    float4 h4 = ((const float4*)HtH)[hwq];
    float4 b4 = ((const float4*)bias)[idx];
    float4 p0 = ((const float4*)g_p1[0])[idx];
    float4 p1 = ((const float4*)g_p1[1])[idx];
    float4 p2 = ((const float4*)g_p1[2])[idx];
    float4 p3 = ((const float4*)g_p1[3])[idx];
    float4 r;
    r.x = fminf(fmaxf(x4.x - tau*(h4.x*x4.x - b4.x) - (p0.x+p1.x+p2.x+p3.x), 0.f), 1.f);
    r.y = fminf(fmaxf(x4.y - tau*(h4.y*x4.y - b4.y) - (p0.y+p1.y+p2.y+p3.y), 0.f), 1.f);
    r.z = fminf(fmaxf(x4.z - tau*(h4.z*x4.z - b4.z) - (p0.z+p1.z+p2.z+p3.z), 0.f), 1.f);
    r.w = fminf(fmaxf(x4.w - tau*(h4.w*x4.w - b4.w) - (p0.w+p1.w+p2.w+p3.w), 0.f), 1.f);
    ((float4*)out0)[idx] = r;
}

// ---------------- pass 2 (R8 exact — proven 50us): grid 2048, 4-row tiles ----
// out1 = clip(sig*conv(2*out0 - x) + u, -lam, lam)
__global__ void __launch_bounds__(256) k_pass2(
    const float* __restrict__ x_in,
    const float* __restrict__ u_in,
    const float* __restrict__ w,
    const float* __restrict__ out0,
    float* __restrict__ out1)
{
    __shared__ float st[6][258];     // rows i0-1..i0+4, data cols 1..256
    const int t    = threadIdx.x;
    const int fg   = blockIdx.x & 3;
    const int tile = (blockIdx.x >> 2) & 63;
    const int b    = blockIdx.x >> 8;
    const int i0   = tile * 4;
    const float sig = g_sigma, lam = g_lambda;

    if (t < 6) { st[t][0] = 0.f; st[t][257] = 0.f; }
    #pragma unroll
    for (int rr = 0; rr < 6; rr++) {
        int gi = i0 - 1 + rr;
        st[rr][t + 1] = (gi >= 0 && gi < Hh)
            ? 2.f * out0[b*HW + gi*Ww + t] - x_in[b*HW + gi*Ww + t] : 0.f;
    }
    __syncthreads();

    const int qc = t & 63;          // cols 4qc..4qc+3
    const int rl = t >> 6;          // own local row (0..3)

    float wv[3][6];
    #pragma unroll
    for (int rr = 0; rr < 3; rr++)
        #pragma unroll
        for (int cc = 0; cc < 6; cc++)
            wv[rr][cc] = st[rl + rr][4*qc + cc];

    const int gi = i0 + rl;
    for (int ff = 0; ff < 16; ff++) {
        const int f = fg * 16 + ff;
        float wf[3][3];
        #pragma unroll
        for (int p = 0; p < 3; p++)
            #pragma unroll
            for (int qq = 0; qq < 3; qq++)
                wf[p][qq] = __ldg(&w[f*9 + p*3 + qq]);

        size_t base = ((size_t)(b*Fn + f)*Hh + gi)*Ww + 4*qc;
        float uv[4];
        ld4cs(uv, &u_in[base]);
        float o[4];
        #pragma unroll
        for (int cc0 = 0; cc0 < 4; cc0++) {
            float y = 0.f;
            #pragma unroll
            for (int p = 0; p < 3; p++)
                #pragma unroll
                for (int qq = 0; qq < 3; qq++)
                    y = fmaf(wf[p][qq], wv[p][cc0 + qq], y);
            float v = sig * y + uv[cc0];
            o[cc0] = fminf(fmaxf(v, -lam), lam);
        }
        st4cs(&out1[base], o);
    }
}

// ---------------- launch ------------------------------------------------------
extern "C" void kernel_launch(void* const* d_in, const int* in_sizes, int n_in,
                              void* d_out, int out_size)
{
    const float* x_in  = (const float*)d_in[0];
    const float* u_in  = (const float*)d_in[1];
    const float* bias  = (const float*)d_in[2];
    const float* beta  = (const float*)d_in[3];
    const float* lambd = (const float*)d_in[4];
    const float* HtH   = (const float*)d_in[5];
    const float* w     = (const float*)d_in[6];
    const float* lsig  = (const float*)d_in[7];

    float* out0 = (float*)d_out;
    float* out1 = out0 + (size_t)Bn * HW;

    k_nop<<<1, 32>>>();   // 2 nops keep ncu's captured launch (index 3)
    k_nop<<<1, 32>>>();   // on the new k_pass1
    k_power<<<PBLK, 256>>>(w, beta, lambd, lsig);
    k_pass1<<<2048, 256>>>(u_in, w);
    k_p1c<<<512, 256>>>(x_in, bias, HtH, out0);
    k_pass2<<<2048, 256>>>(x_in, u_in, w, out0, out1);
}

// round 17
// speedup vs baseline: 1.2343x; 1.2343x over previous
#include <cuda_runtime.h>

#define Hh 256
#define Ww 256
#define Bn 8
#define Fn 64
#define HW 65536
#define PBLK 128

// ---------------- device globals -------------------------------------------
__device__ float g_xA[HW];
__device__ float g_xB[HW];
__device__ float4 g_part4[2][PBLK];
__device__ float g_p1[4][Bn * HW];       // pass1 filter-group partials (8MB)
__device__ float g_sigma, g_lambda, g_tau;
__device__ unsigned g_barcnt = 0;        // invariant 0 between barriers
__device__ unsigned g_bargen = 0;        // monotone generation (replay-safe)

// ---------------- float4 helpers ---------------------------------------------
__device__ __forceinline__ void ld4cs(float d[4], const float* p) {
    float4 v = __ldcs((const float4*)p); d[0]=v.x; d[1]=v.y; d[2]=v.z; d[3]=v.w;
}
__device__ __forceinline__ void st4cs(float* p, const float d[4]) {
    __stcs((float4*)p, make_float4(d[0], d[1], d[2], d[3]));
}

// ---------------- grid barrier over the PBLK power blocks --------------------
__device__ __forceinline__ void grid_bar()
{
    __syncthreads();
    if (threadIdx.x == 0) {
        volatile unsigned* genp = &g_bargen;
        unsigned gen = *genp;              // read BEFORE arriving
        unsigned a = atomicAdd(&g_barcnt, 1u);
        if (a == PBLK - 1u) {
            atomicExch(&g_barcnt, 0u);     // reset BEFORE releasing
            __threadfence();
            atomicExch(&g_bargen, gen + 1u);
        } else {
            while (*genp == gen) { __nanosleep(32); }
        }
        __threadfence();
    }
    __syncthreads();
}

// ---------------- one application of M (rolling 5x5 register window) ---------
template<int N, int OWN>
__device__ __forceinline__ void apply_app(
    const float* __restrict__ src, float* __restrict__ dst,
    int dst_lo_g, int src_lo_g, int j, const float G[25],
    const float* __restrict__ sK, const float* __restrict__ sCL,
    const float* __restrict__ sCR, float& sacc, float* __restrict__ gdst)
{
    float win[5][5];
    #pragma unroll
    for (int r = 0; r < 4; r++)
        #pragma unroll
        for (int c = 0; c < 5; c++)
            win[r+1][c] = src[r*260 + j + c];

    #pragma unroll
    for (int rr = 0; rr < N; rr++) {
        const int r = dst_lo_g + rr;
        #pragma unroll
        for (int q = 0; q < 4; q++)
            #pragma unroll
            for (int c = 0; c < 5; c++)
                win[q][c] = win[q+1][c];
        #pragma unroll
        for (int c = 0; c < 5; c++)
            win[4][c] = src[(rr + 4)*260 + j + c];

        float z = 0.f;
        if (r >= 0 && r < 256) {
            #pragma unroll
            for (int di = 0; di < 5; di++)
                #pragma unroll
                for (int dj = 0; dj < 5; dj++)
                    z = fmaf(G[di*5 + dj], win[di][dj], z);

            if (r == 0 || r == 255) {
                #pragma unroll
                for (int ai = 0; ai < 3; ai++)
                    #pragma unroll
                    for (int aj = 0; aj < 3; aj++) {
                        int pi = r + ai - 1, pj = j + aj - 1;
                        if (pi < 0 || pi > 255 || pj < 0 || pj > 255) {
                            #pragma unroll
                            for (int bi = 0; bi < 3; bi++)
                                #pragma unroll
                                for (int bj = 0; bj < 3; bj++) {
                                    int qi = pi + bi - 1, qj = pj + bj - 1;
                                    if (qi >= 0 && qi < 256 && qj >= 0 && qj < 256)
                                        z -= sK[(ai*3+aj)*9 + bi*3 + bj] *
                                             src[(qi - src_lo_g)*260 + qj + 2];
                                }
                        }
                    }
            } else if (j == 0) {
                #pragma unroll
                for (int d = 0; d < 5; d++) {
                    int qi = r + d - 2;
                    if (qi >= 0 && qi < 256)
                        z = fmaf(-sCL[d], win[d][2], z);
                }
            } else if (j == 255) {
                #pragma unroll
                for (int d = 0; d < 5; d++) {
                    int qi = r + d - 2;
                    if (qi >= 0 && qi < 256)
                        z = fmaf(-sCR[d], win[d][2], z);
                }
            }
        }
        dst[rr*260 + 2 + j] = z;
        if (rr == OWN || rr == OWN + 1) {
            sacc = fmaf(z, z, sacc);
            if (gdst) gdst[r*256 + j] = z;
        }
    }
}

// ---------------- power iteration (R6 — proven 32us) --------------------------
__global__ void __launch_bounds__(256) k_power(
    const float* __restrict__ w, const float* __restrict__ beta,
    const float* __restrict__ lambd, const float* __restrict__ lsig)
{
    __shared__ float pool[6380];
    float* bufA = pool;                 // 14 x 260
    float* bufB = pool + 3640;          // 10 x 260
    float* sK   = pool + 6240;          // 81
    float* sG   = pool + 6321;          // 25
    float* sCL  = pool + 6346;          // 5
    float* sCR  = pool + 6351;          // 5
    float* red  = pool + 6356;          // 3 x 8

    const int t = threadIdx.x, blk = blockIdx.x;
    const int j = t, lane = t & 31, warp = t >> 5;
    const int i0 = blk * 2;

    if (t < 81) {
        int a9 = t / 9, b9 = t % 9;
        int ai = a9 / 3, aj = a9 % 3;
        int bi = b9 / 3, bj = b9 % 3;
        float s = 0.f;
        #pragma unroll 8
        for (int f = 0; f < Fn; f++)
            s += w[f*9 + (2-ai)*3 + (2-aj)] * w[f*9 + bi*3 + bj];
        sK[t] = s;
    }
    __syncthreads();
    if (t < 25) {
        int di = t / 5 - 2, dj = t % 5 - 2;
        float s = 0.f;
        for (int a9 = 0; a9 < 9; a9++) {
            int ai = a9/3 - 1, aj = a9%3 - 1;
            int bi = di - ai, bj = dj - aj;
            if (bi >= -1 && bi <= 1 && bj >= -1 && bj <= 1)
                s += sK[a9*9 + (bi+1)*3 + (bj+1)];
        }
        sG[t] = s;
    } else if (t >= 32 && t < 37) {
        int d = t - 32;
        float s = 0.f;
        for (int ai = 0; ai < 3; ai++) {
            int bi = d - ai;
            if (bi >= 0 && bi <= 2) s += sK[(ai*3 + 0)*9 + bi*3 + 2];
        }
        sCL[d] = s;
    } else if (t >= 40 && t < 45) {
        int d = t - 40;
        float s = 0.f;
        for (int ai = 0; ai < 3; ai++) {
            int bi = d - ai;
            if (bi >= 0 && bi <= 2) s += sK[(ai*3 + 2)*9 + bi*3 + 0];
        }
        sCR[d] = s;
    } else if (t == 255 && blk == 0) {
        g_sigma  = expf(lsig[0]) + 0.05f;
        g_lambda = lambd[0];
    }
    if (t >= 64 && t < 78) {
        int q = t - 64;
        bufA[q*260] = bufA[q*260+1] = bufA[q*260+258] = bufA[q*260+259] = 0.f;
    } else if (t >= 96 && t < 106) {
        int q = t - 96;
        bufB[q*260] = bufB[q*260+1] = bufB[q*260+258] = bufB[q*260+259] = 0.f;
    }
    __syncthreads();

    float G[25];
    #pragma unroll
    for (int k = 0; k < 25; k++) G[k] = sG[k];

    g_xA[i0*256 + j]     = 1.f / 256.f;
    g_xA[(i0+1)*256 + j] = 1.f / 256.f;
    __threadfence();
    grid_bar();

    float val = 1.f, inv = 1.f;
    int iter = 0, par = 0;
    bool done = false;

    while (!done) {
        const float* srcg = par ? g_xB : g_xA;
        float*       dstg = par ? g_xA : g_xB;

        __syncthreads();
        #pragma unroll
        for (int rr = 0; rr < 14; rr++) {
            int gi = i0 - 6 + rr;
            bufA[rr*260 + 2 + j] =
                (gi >= 0 && gi < 256) ? inv * __ldcg(&srcg[gi*256 + j]) : 0.f;
        }
        __syncthreads();

        float s1 = 0.f, s2 = 0.f, s3 = 0.f;
        apply_app<10,4>(bufA, bufB, i0-4, i0-6, j, G, sK, sCL, sCR, s1, nullptr);
        __syncthreads();
        apply_app<6,2>(bufB, bufA, i0-2, i0-4, j, G, sK, sCL, sCR, s2, nullptr);
        __syncthreads();
        apply_app<2,0>(bufA, bufB, i0,   i0-2, j, G, sK, sCL, sCR, s3, dstg);

        #pragma unroll
        for (int o = 16; o > 0; o >>= 1) {
            s1 += __shfl_xor_sync(0xffffffffu, s1, o);
            s2 += __shfl_xor_sync(0xffffffffu, s2, o);
            s3 += __shfl_xor_sync(0xffffffffu, s3, o);
        }
        if (lane == 0) { red[0*8+warp] = s1; red[1*8+warp] = s2; red[2*8+warp] = s3; }
        __syncthreads();
        if (t == 0) {
            float a = 0.f, b = 0.f, c = 0.f;
            #pragma unroll
            for (int w8 = 0; w8 < 8; w8++) {
                a += red[0*8+w8]; b += red[1*8+w8]; c += red[2*8+w8];
            }
            g_part4[par][blk] = make_float4(a, b, c, 0.f);
        }
        __threadfence();
        grid_bar();

        float px = 0.f, py = 0.f, pz = 0.f;
        if (t < 128) {
            px = __ldcg(&g_part4[par][t].x);
            py = __ldcg(&g_part4[par][t].y);
            pz = __ldcg(&g_part4[par][t].z);
        }
        #pragma unroll
        for (int o = 16; o > 0; o >>= 1) {
            px += __shfl_xor_sync(0xffffffffu, px, o);
            py += __shfl_xor_sync(0xffffffffu, py, o);
            pz += __shfl_xor_sync(0xffffffffu, pz, o);
        }
        __syncthreads();
        if (lane == 0 && t < 128) { red[0*8+warp] = px; red[1*8+warp] = py; red[2*8+warp] = pz; }
        __syncthreads();
        float S1 = red[0*8+0] + red[0*8+1] + red[0*8+2] + red[0*8+3];
        float S2 = red[1*8+0] + red[1*8+1] + red[1*8+2] + red[1*8+3];
        float S3 = red[2*8+0] + red[2*8+1] + red[2*8+2] + red[2*8+3];

        float v1 = sqrtf(S1);
        float v2 = sqrtf(S2) / v1;
        float v3 = sqrtf(S3) / sqrtf(S2);
        float rel;
        iter++; rel = fabsf(v1 - val) / val; val = v1;
        if (iter >= 300 || rel < 1e-4f) { done = true; }
        else {
            iter++; rel = fabsf(v2 - val) / val; val = v2;
            if (iter >= 300 || rel < 1e-4f) { done = true; }
            else {
                iter++; rel = fabsf(v3 - val) / val; val = v3;
                if (iter >= 300 || rel < 1e-4f) done = true;
            }
        }
        inv = 1.f / sqrtf(S3);
        par ^= 1;
    }

    if (blk == 0 && t == 0) {
        float sg = expf(lsig[0]) + 0.05f;
        g_tau = 0.99f / (beta[0] * 0.5f + sg * val);
    }
}

// ---------------- pass 1: smem-free, 2 rows x 4 cols, scalar halos ------------
// partial[fg] = tau * sum_{f in fg} convT(u_f); grid 1024 = 8b x 32rt x 4fg
__global__ void __launch_bounds__(256) k_pass1(
    const float* __restrict__ u_in, const float* __restrict__ w)
{
    const int t   = threadIdx.x;
    const int q   = blockIdx.x;
    const int fg  = q & 3;
    const int rt  = (q >> 2) & 31;
    const int b   = q >> 7;
    const int i0  = rt * 8;
    const int qc  = t & 63;         // cols 4qc..4qc+3
    const int rl  = t >> 6;         // row pair 0..3
    const int gi0 = i0 + 2 * rl;    // own rows gi0, gi0+1
    const int col = 4 * qc;
    const float tau = g_tau;

    float acc[2][4];
    #pragma unroll
    for (int orow = 0; orow < 2; orow++)
        #pragma unroll
        for (int cc = 0; cc < 4; cc++) acc[orow][cc] = 0.f;

    for (int ff = 0; ff < 16; ff++) {
        const int f = fg * 16 + ff;
        const float* uf = u_in + (size_t)(b*Fn + f) * HW;

        // 4x6 register window: 4 LDG.128 + up to 8 L1-hit scalar halos (R15 style)
        float win[4][6];
        #pragma unroll
        for (int rr = 0; rr < 4; rr++) {
            int r = gi0 - 1 + rr;
            if (r >= 0 && r < Hh) {
                const float* row = uf + r * Ww + col;
                float4 v = *(const float4*)row;
                win[rr][1] = v.x; win[rr][2] = v.y; win[rr][3] = v.z; win[rr][4] = v.w;
                win[rr][0] = (col > 0)      ? row[-1] : 0.f;
                win[rr][5] = (col + 4 < Ww) ? row[4]  : 0.f;
            } else {
                #pragma unroll
                for (int k = 0; k < 6; k++) win[rr][k] = 0.f;
            }
        }

        float m[3][3];
        #pragma unroll
        for (int au = 0; au < 3; au++)
            #pragma unroll
            for (int ac = 0; ac < 3; ac++)
                m[au][ac] = tau * __ldg(&w[f*9 + (2-au)*3 + (2-ac)]);

        #pragma unroll
        for (int orow = 0; orow < 2; orow++)
            #pragma unroll
            for (int cc = 0; cc < 4; cc++)
                #pragma unroll
                for (int au = 0; au < 3; au++)
                    #pragma unroll
                    for (int ac = 0; ac < 3; ac++)
                        acc[orow][cc] = fmaf(m[au][ac], win[orow + au][cc + ac],
                                             acc[orow][cc]);
    }

    #pragma unroll
    for (int orow = 0; orow < 2; orow++)
        *(float4*)&g_p1[fg][b*HW + (gi0 + orow)*Ww + col] =
            make_float4(acc[orow][0], acc[orow][1], acc[orow][2], acc[orow][3]);
}

// ---------------- combine: out0 = clip(x - tau*(HtH.x - bias) - sum(p)) -------
__global__ void k_p1c(const float* __restrict__ x_in,
                      const float* __restrict__ bias,
                      const float* __restrict__ HtH,
                      float* __restrict__ out0)
{
    int idx = blockIdx.x * 256 + threadIdx.x;   // float4 index; 512*256 = 131072
    int hwq = idx & (HW/4 - 1);                 // position within one image (float4)
    float tau = g_tau;
    float4 x4 = ((const float4*)x_in)[idx];
    float4 h4 = ((const float4*)HtH)[hwq];
    float4 b4 = ((const float4*)bias)[idx];
    float4 p0 = ((const float4*)g_p1[0])[idx];
    float4 p1 = ((const float4*)g_p1[1])[idx];
    float4 p2 = ((const float4*)g_p1[2])[idx];
    float4 p3 = ((const float4*)g_p1[3])[idx];
    float4 r;
    r.x = fminf(fmaxf(x4.x - tau*(h4.x*x4.x - b4.x) - (p0.x+p1.x+p2.x+p3.x), 0.f), 1.f);
    r.y = fminf(fmaxf(x4.y - tau*(h4.y*x4.y - b4.y) - (p0.y+p1.y+p2.y+p3.y), 0.f), 1.f);
    r.z = fminf(fmaxf(x4.z - tau*(h4.z*x4.z - b4.z) - (p0.z+p1.z+p2.z+p3.z), 0.f), 1.f);
    r.w = fminf(fmaxf(x4.w - tau*(h4.w*x4.w - b4.w) - (p0.w+p1.w+p2.w+p3.w), 0.f), 1.f);
    ((float4*)out0)[idx] = r;
}

// ---------------- pass 2 (R8 exact — proven 50us): grid 2048, 4-row tiles ----
// out1 = clip(sig*conv(2*out0 - x) + u, -lam, lam)
__global__ void __launch_bounds__(256) k_pass2(
    const float* __restrict__ x_in,
    const float* __restrict__ u_in,
    const float* __restrict__ w,
    const float* __restrict__ out0,
    float* __restrict__ out1)
{
    __shared__ float st[6][258];     // rows i0-1..i0+4, data cols 1..256
    const int t    = threadIdx.x;
    const int fg   = blockIdx.x & 3;
    const int tile = (blockIdx.x >> 2) & 63;
    const int b    = blockIdx.x >> 8;
    const int i0   = tile * 4;
    const float sig = g_sigma, lam = g_lambda;

    if (t < 6) { st[t][0] = 0.f; st[t][257] = 0.f; }
    #pragma unroll
    for (int rr = 0; rr < 6; rr++) {
        int gi = i0 - 1 + rr;
        st[rr][t + 1] = (gi >= 0 && gi < Hh)
            ? 2.f * out0[b*HW + gi*Ww + t] - x_in[b*HW + gi*Ww + t] : 0.f;
    }
    __syncthreads();

    const int qc = t & 63;          // cols 4qc..4qc+3
    const int rl = t >> 6;          // own local row (0..3)

    float wv[3][6];
    #pragma unroll
    for (int rr = 0; rr < 3; rr++)
        #pragma unroll
        for (int cc = 0; cc < 6; cc++)
            wv[rr][cc] = st[rl + rr][4*qc + cc];

    const int gi = i0 + rl;
    for (int ff = 0; ff < 16; ff++) {
        const int f = fg * 16 + ff;
        float wf[3][3];
        #pragma unroll
        for (int p = 0; p < 3; p++)
            #pragma unroll
            for (int qq = 0; qq < 3; qq++)
                wf[p][qq] = __ldg(&w[f*9 + p*3 + qq]);

        size_t base = ((size_t)(b*Fn + f)*Hh + gi)*Ww + 4*qc;
        float uv[4];
        ld4cs(uv, &u_in[base]);
        float o[4];
        #pragma unroll
        for (int cc0 = 0; cc0 < 4; cc0++) {
            float y = 0.f;
            #pragma unroll
            for (int p = 0; p < 3; p++)
                #pragma unroll
                for (int qq = 0; qq < 3; qq++)
                    y = fmaf(wf[p][qq], wv[p][cc0 + qq], y);
            float v = sig * y + uv[cc0];
            o[cc0] = fminf(fmaxf(v, -lam), lam);
        }
        st4cs(&out1[base], o);
    }
}

// ---------------- launch ------------------------------------------------------
extern "C" void kernel_launch(void* const* d_in, const int* in_sizes, int n_in,
                              void* d_out, int out_size)
{
    const float* x_in  = (const float*)d_in[0];
    const float* u_in  = (const float*)d_in[1];
    const float* bias  = (const float*)d_in[2];
    const float* beta  = (const float*)d_in[3];
    const float* lambd = (const float*)d_in[4];
    const float* HtH   = (const float*)d_in[5];
    const float* w     = (const float*)d_in[6];
    const float* lsig  = (const float*)d_in[7];

    float* out0 = (float*)d_out;
    float* out1 = out0 + (size_t)Bn * HW;

    k_power<<<PBLK, 256>>>(w, beta, lambd, lsig);
    k_pass1<<<1024, 256>>>(u_in, w);
    k_p1c<<<512, 256>>>(x_in, bias, HtH, out0);
    k_pass2<<<2048, 256>>>(x_in, u_in, w, out0, out1);
}